// round 1
// baseline (speedup 1.0000x reference)
#include <cuda_runtime.h>
#include <cuda_bf16.h>
#include <math.h>

#define HIDDEN 2048
#define N_HEADS 32
#define N_KV 4
#define HEAD_DIM 128
#define B_SZ 2
#define S_LEN 2048
#define TOKENS (B_SZ * S_LEN)            // 4096
#define QKV_DIM ((N_HEADS + 2 * N_KV) * HEAD_DIM)  // 5120
#define Q_SIZE (N_HEADS * HEAD_DIM)      // 4096
#define KV_SIZE (N_KV * HEAD_DIM)        // 512

// Scratch (static device allocations are the sanctioned workaround)
__device__ float g_qkv[(size_t)TOKENS * QKV_DIM];   // ~84 MB
__device__ float g_attn[(size_t)TOKENS * Q_SIZE];   // ~67 MB

// ---------------------------------------------------------------------------
// Tiled fp32 GEMM:  C[M,N] = A[M,K] * B[N,K]^T   (both row-major, K contiguous)
// BM=BN=128, BK=16, 256 threads, 8x8 per thread.
// ---------------------------------------------------------------------------
__global__ __launch_bounds__(256) void gemm_nt(
    const float* __restrict__ A, const float* __restrict__ Bm,
    float* __restrict__ C, int M, int N, int K)
{
    __shared__ float As[16][132];
    __shared__ float Bs[16][132];

    const int tid = threadIdx.x;
    const int tx = tid & 15;          // 0..15
    const int ty = tid >> 4;          // 0..15
    const int m0 = blockIdx.y * 128;
    const int n0 = blockIdx.x * 128;

    const int lr = tid >> 2;          // 0..63 loader row
    const int lc = tid & 3;           // 0..3  loader float4 col

    float acc[8][8];
#pragma unroll
    for (int i = 0; i < 8; i++)
#pragma unroll
        for (int j = 0; j < 8; j++) acc[i][j] = 0.f;

    for (int k0 = 0; k0 < K; k0 += 16) {
#pragma unroll
        for (int rr = 0; rr < 2; rr++) {
            int row = lr + 64 * rr;
            float4 a = *(const float4*)&A[(size_t)(m0 + row) * K + k0 + 4 * lc];
            As[4 * lc + 0][row] = a.x;
            As[4 * lc + 1][row] = a.y;
            As[4 * lc + 2][row] = a.z;
            As[4 * lc + 3][row] = a.w;
            float4 b = *(const float4*)&Bm[(size_t)(n0 + row) * K + k0 + 4 * lc];
            Bs[4 * lc + 0][row] = b.x;
            Bs[4 * lc + 1][row] = b.y;
            Bs[4 * lc + 2][row] = b.z;
            Bs[4 * lc + 3][row] = b.w;
        }
        __syncthreads();

#pragma unroll
        for (int k = 0; k < 16; k++) {
            float af[8], bf[8];
            *(float4*)&af[0] = *(float4*)&As[k][ty * 8];
            *(float4*)&af[4] = *(float4*)&As[k][ty * 8 + 4];
            *(float4*)&bf[0] = *(float4*)&Bs[k][tx * 8];
            *(float4*)&bf[4] = *(float4*)&Bs[k][tx * 8 + 4];
#pragma unroll
            for (int i = 0; i < 8; i++)
#pragma unroll
                for (int j = 0; j < 8; j++)
                    acc[i][j] = fmaf(af[i], bf[j], acc[i][j]);
        }
        __syncthreads();
    }

#pragma unroll
    for (int i = 0; i < 8; i++) {
        size_t crow = (size_t)(m0 + ty * 8 + i) * N + n0 + tx * 8;
        *(float4*)&C[crow]     = make_float4(acc[i][0], acc[i][1], acc[i][2], acc[i][3]);
        *(float4*)&C[crow + 4] = make_float4(acc[i][4], acc[i][5], acc[i][6], acc[i][7]);
    }
}

// ---------------------------------------------------------------------------
// Per-(token, head) RMSNorm + RoPE, in place on g_qkv.
// 128 threads/block, grid = TOKENS * (N_HEADS + N_KV)
// ---------------------------------------------------------------------------
__global__ __launch_bounds__(128) void norm_rope(
    float* __restrict__ qkv, const int* __restrict__ positions,
    const float* __restrict__ qw, const float* __restrict__ kw)
{
    const int blk = blockIdx.x;
    const int t = blk / (N_HEADS + N_KV);
    const int hh = blk % (N_HEADS + N_KV);
    float* ptr;
    const float* w;
    if (hh < N_HEADS) {
        ptr = qkv + (size_t)t * QKV_DIM + hh * HEAD_DIM;
        w = qw;
    } else {
        ptr = qkv + (size_t)t * QKV_DIM + Q_SIZE + (hh - N_HEADS) * HEAD_DIM;
        w = kw;
    }
    const int tid = threadIdx.x;
    __shared__ float xs[128];
    __shared__ float red[4];

    float x = ptr[tid];
    float ss = x * x;
#pragma unroll
    for (int o = 16; o > 0; o >>= 1) ss += __shfl_xor_sync(0xffffffffu, ss, o);
    if ((tid & 31) == 0) red[tid >> 5] = ss;
    __syncthreads();
    float tot = red[0] + red[1] + red[2] + red[3];
    float r = rsqrtf(tot * (1.0f / 128.0f) + 1e-6f);
    xs[tid] = x * r * w[tid];
    __syncthreads();

    if (tid < 64) {
        int pos = positions[t];
        // inv_freq = theta^(-i/64);  ln(1e6) = 13.815510557964274
        double invf = exp(-(double)tid * (13.815510557964274 / 64.0));
        double ang = (double)pos * invf;
        double sd, cd;
        sincos(ang, &sd, &cd);
        float c = (float)cd, s = (float)sd;
        float x1 = xs[tid], x2 = xs[tid + 64];
        ptr[tid]      = x1 * c - x2 * s;
        ptr[tid + 64] = x2 * c + x1 * s;
    }
}

// ---------------------------------------------------------------------------
// Flash attention, fp32, causal, GQA (group = 8).
// 64x64 tiles, d = 128. 256 threads. Q/K stored transposed [d][row] in smem.
// grid = (S/64, B * N_HEADS)
// ---------------------------------------------------------------------------
#define QK_STRIDE 68   // 64 + 4 pad, keeps float4 alignment

__global__ __launch_bounds__(256) void flash_attn(
    const float* __restrict__ qkv, float* __restrict__ attn_out)
{
    extern __shared__ float sm[];
    float* Qts = sm;                          // [128][68]
    float* Kts = Qts + 128 * QK_STRIDE;       // [128][68]
    float* Vs  = Kts + 128 * QK_STRIDE;       // [64][128]
    float* Ps  = Vs + 64 * 128;               // [64][64]

    const int qt = blockIdx.x;                // q-tile 0..31
    const int bh = blockIdx.y;                // 0..63
    const int b = bh >> 5;
    const int h = bh & 31;
    const int kvh = h >> 3;
    const int tid = threadIdx.x;
    const int tx = tid & 15;
    const int ty = tid >> 4;
    const int qm0 = qt * 64;
    const float scale = 0.08838834764831845f; // 1/sqrt(128)

    const int lr = tid >> 2;                  // 0..63
    const int lc = tid & 3;                   // 0..3

    // Load Q tile transposed (with softmax scale folded in)
    const float* qbase = qkv + (size_t)(b * S_LEN + qm0) * QKV_DIM + h * HEAD_DIM;
#pragma unroll
    for (int i = 0; i < 8; i++) {
        int d4 = lc + 4 * i;
        float4 v = *(const float4*)&qbase[(size_t)lr * QKV_DIM + d4 * 4];
        Qts[(d4 * 4 + 0) * QK_STRIDE + lr] = v.x * scale;
        Qts[(d4 * 4 + 1) * QK_STRIDE + lr] = v.y * scale;
        Qts[(d4 * 4 + 2) * QK_STRIDE + lr] = v.z * scale;
        Qts[(d4 * 4 + 3) * QK_STRIDE + lr] = v.w * scale;
    }
    __syncthreads();

    float m_i[4], l_i[4], O[4][8];
#pragma unroll
    for (int i = 0; i < 4; i++) {
        m_i[i] = -1e30f;
        l_i[i] = 0.f;
#pragma unroll
        for (int c = 0; c < 8; c++) O[i][c] = 0.f;
    }

    const float* kbase_all = qkv + (size_t)(b * S_LEN) * QKV_DIM + Q_SIZE + kvh * HEAD_DIM;
    const float* vbase_all = kbase_all + KV_SIZE;

    for (int kt = 0; kt <= qt; kt++) {
        const float* kb = kbase_all + (size_t)kt * 64 * QKV_DIM;
        const float* vb = vbase_all + (size_t)kt * 64 * QKV_DIM;
#pragma unroll
        for (int i = 0; i < 8; i++) {
            int d4 = lc + 4 * i;
            float4 kv4 = *(const float4*)&kb[(size_t)lr * QKV_DIM + d4 * 4];
            Kts[(d4 * 4 + 0) * QK_STRIDE + lr] = kv4.x;
            Kts[(d4 * 4 + 1) * QK_STRIDE + lr] = kv4.y;
            Kts[(d4 * 4 + 2) * QK_STRIDE + lr] = kv4.z;
            Kts[(d4 * 4 + 3) * QK_STRIDE + lr] = kv4.w;
            float4 vv4 = *(const float4*)&vb[(size_t)lr * QKV_DIM + d4 * 4];
            *(float4*)&Vs[lr * 128 + d4 * 4] = vv4;
        }
        __syncthreads();

        // S = Q K^T  (4x4 per thread)
        float s[4][4];
#pragma unroll
        for (int i = 0; i < 4; i++)
#pragma unroll
            for (int j = 0; j < 4; j++) s[i][j] = 0.f;

#pragma unroll 4
        for (int d = 0; d < 128; d++) {
            float4 qv = *(float4*)&Qts[d * QK_STRIDE + 4 * ty];
            float4 kv = *(float4*)&Kts[d * QK_STRIDE + 4 * tx];
            float qa[4] = {qv.x, qv.y, qv.z, qv.w};
            float ka[4] = {kv.x, kv.y, kv.z, kv.w};
#pragma unroll
            for (int i = 0; i < 4; i++)
#pragma unroll
                for (int j = 0; j < 4; j++)
                    s[i][j] = fmaf(qa[i], ka[j], s[i][j]);
        }

        if (kt == qt) {
#pragma unroll
            for (int i = 0; i < 4; i++)
#pragma unroll
                for (int j = 0; j < 4; j++)
                    if (4 * tx + j > 4 * ty + i) s[i][j] = -1e30f;
        }

        // Online softmax (rows owned by the 16 lanes sharing ty)
#pragma unroll
        for (int i = 0; i < 4; i++) {
            float mx = s[i][0];
            mx = fmaxf(mx, s[i][1]);
            mx = fmaxf(mx, s[i][2]);
            mx = fmaxf(mx, s[i][3]);
#pragma unroll
            for (int o = 8; o > 0; o >>= 1)
                mx = fmaxf(mx, __shfl_xor_sync(0xffffffffu, mx, o, 16));
            float mnew = fmaxf(m_i[i], mx);
            float alpha = __expf(m_i[i] - mnew);
            float rowsum = 0.f;
#pragma unroll
            for (int j = 0; j < 4; j++) {
                float p = __expf(s[i][j] - mnew);
                s[i][j] = p;
                rowsum += p;
            }
#pragma unroll
            for (int o = 8; o > 0; o >>= 1)
                rowsum += __shfl_xor_sync(0xffffffffu, rowsum, o, 16);
            l_i[i] = l_i[i] * alpha + rowsum;
            m_i[i] = mnew;
#pragma unroll
            for (int c = 0; c < 8; c++) O[i][c] *= alpha;
            *(float4*)&Ps[(4 * ty + i) * 64 + 4 * tx] =
                make_float4(s[i][0], s[i][1], s[i][2], s[i][3]);
        }
        __syncthreads();

        // O += P @ V
#pragma unroll 2
        for (int j = 0; j < 64; j++) {
            float p0 = Ps[(4 * ty + 0) * 64 + j];
            float p1 = Ps[(4 * ty + 1) * 64 + j];
            float p2 = Ps[(4 * ty + 2) * 64 + j];
            float p3 = Ps[(4 * ty + 3) * 64 + j];
            float4 va = *(float4*)&Vs[j * 128 + 8 * tx];
            float4 vbv = *(float4*)&Vs[j * 128 + 8 * tx + 4];
            float vv[8] = {va.x, va.y, va.z, va.w, vbv.x, vbv.y, vbv.z, vbv.w};
#pragma unroll
            for (int c = 0; c < 8; c++) {
                O[0][c] = fmaf(p0, vv[c], O[0][c]);
                O[1][c] = fmaf(p1, vv[c], O[1][c]);
                O[2][c] = fmaf(p2, vv[c], O[2][c]);
                O[3][c] = fmaf(p3, vv[c], O[3][c]);
            }
        }
        __syncthreads();
    }

    // Epilogue: normalize and store [token][h*128 + col]
#pragma unroll
    for (int i = 0; i < 4; i++) {
        float inv = 1.0f / l_i[i];
        size_t row = (size_t)(b * S_LEN + qm0 + 4 * ty + i) * Q_SIZE + h * HEAD_DIM + 8 * tx;
        attn_out[row + 0] = O[i][0] * inv;
        attn_out[row + 1] = O[i][1] * inv;
        attn_out[row + 2] = O[i][2] * inv;
        attn_out[row + 3] = O[i][3] * inv;
        attn_out[row + 4] = O[i][4] * inv;
        attn_out[row + 5] = O[i][5] * inv;
        attn_out[row + 6] = O[i][6] * inv;
        attn_out[row + 7] = O[i][7] * inv;
    }
}

// ---------------------------------------------------------------------------
extern "C" void kernel_launch(void* const* d_in, const int* in_sizes, int n_in,
                              void* d_out, int out_size)
{
    const float* hidden    = (const float*)d_in[0];
    const int*   positions = (const int*)d_in[1];
    const float* w_qkv     = (const float*)d_in[2];
    const float* w_o       = (const float*)d_in[3];
    const float* q_norm_w  = (const float*)d_in[4];
    const float* k_norm_w  = (const float*)d_in[5];
    float* out = (float*)d_out;

    float* qkv;
    float* attn;
    cudaGetSymbolAddress((void**)&qkv, g_qkv);
    cudaGetSymbolAddress((void**)&attn, g_attn);

    // 1) QKV projection: [4096,2048] x [5120,2048]^T -> [4096,5120]
    gemm_nt<<<dim3(QKV_DIM / 128, TOKENS / 128), 256>>>(
        hidden, w_qkv, qkv, TOKENS, QKV_DIM, HIDDEN);

    // 2) RMSNorm + RoPE on q and k heads, in place
    norm_rope<<<TOKENS * (N_HEADS + N_KV), 128>>>(qkv, positions, q_norm_w, k_norm_w);

    // 3) Causal flash attention
    const int flash_smem = (2 * 128 * QK_STRIDE + 64 * 128 + 64 * 64) * sizeof(float);
    cudaFuncSetAttribute(flash_attn, cudaFuncAttributeMaxDynamicSharedMemorySize, flash_smem);
    flash_attn<<<dim3(S_LEN / 64, B_SZ * N_HEADS), 256, flash_smem>>>(qkv, attn);

    // 4) Output projection: [4096,4096] x [2048,4096]^T -> [4096,2048]
    gemm_nt<<<dim3(HIDDEN / 128, TOKENS / 128), 256>>>(
        attn, w_o, out, TOKENS, HIDDEN, Q_SIZE);
}

// round 3
// speedup vs baseline: 1.5099x; 1.5099x over previous
#include <cuda_runtime.h>
#include <cuda_bf16.h>
#include <math.h>
#include <cstdint>

#define HIDDEN 2048
#define N_HEADS 32
#define N_KV 4
#define HEAD_DIM 128
#define B_SZ 2
#define S_LEN 2048
#define TOKENS (B_SZ * S_LEN)            // 4096
#define QKV_DIM ((N_HEADS + 2 * N_KV) * HEAD_DIM)  // 5120
#define Q_SIZE (N_HEADS * HEAD_DIM)      // 4096
#define KV_SIZE (N_KV * HEAD_DIM)        // 512

// Scratch
__device__ float g_qkv[(size_t)TOKENS * QKV_DIM];   // ~84 MB
__device__ float g_attn[(size_t)TOKENS * Q_SIZE];   // ~67 MB

// ---------------------------------------------------------------------------
// Helpers
// ---------------------------------------------------------------------------
static __device__ __forceinline__ uint32_t smem_u32(const void* p) {
    uint32_t a;
    asm("{ .reg .u64 t; cvta.to.shared.u64 t, %1; cvt.u32.u64 %0, t; }" : "=r"(a) : "l"(p));
    return a;
}
static __device__ __forceinline__ uint32_t f2tf32(float x) {
    uint32_t r;
    asm("cvt.rna.tf32.f32 %0, %1;" : "=r"(r) : "f"(x));
    return r;
}
#define CP_ASYNC16(dst, src) \
    asm volatile("cp.async.cg.shared.global [%0], [%1], 16;" :: "r"(dst), "l"(src) : "memory")
#define CP_COMMIT() asm volatile("cp.async.commit_group;" ::: "memory")
#define CP_WAIT(n)  asm volatile("cp.async.wait_group %0;" :: "n"(n) : "memory")

// m16n8k8 tf32 mma.sync (row.col): D += A * B
static __device__ __forceinline__ void mma_tf32(
    float* c, const uint32_t* a, const uint32_t* b)
{
    asm volatile(
        "mma.sync.aligned.m16n8k8.row.col.f32.tf32.tf32.f32 "
        "{%0,%1,%2,%3}, {%4,%5,%6,%7}, {%8,%9}, {%0,%1,%2,%3};"
        : "+f"(c[0]), "+f"(c[1]), "+f"(c[2]), "+f"(c[3])
        : "r"(a[0]), "r"(a[1]), "r"(a[2]), "r"(a[3]), "r"(b[0]), "r"(b[1]));
}

// ---------------------------------------------------------------------------
// tf32 mma.sync GEMM: C[M,N] = A[M,K] * B[N,K]^T (row-major, K contiguous)
// CTA 128x128, K-chunk 32, cp.async double buffer, 8 warps x (64x32 tile).
// ---------------------------------------------------------------------------
#define GBM 128
#define GBN 128
#define GBK 32
#define KPAD 40                           // floats per smem row (160 B)
#define STAGE_FLOATS ((GBM + GBN) * KPAD) // 10240
#define STAGE_BYTES (STAGE_FLOATS * 4)    // 40960
#define GEMM_SMEM (2 * STAGE_BYTES)       // 81920

__global__ __launch_bounds__(256) void gemm_tc(
    const float* __restrict__ A, const float* __restrict__ Bw,
    float* __restrict__ C, int M, int N, int K)
{
    extern __shared__ float smf[];
    const uint32_t smb = smem_u32(smf);
    const int tid = threadIdx.x;
    const int wid = tid >> 5;
    const int lane = tid & 31;
    const int group = lane >> 2;          // 0..7
    const int tig = lane & 3;             // 0..3
    const int wm = wid >> 2;              // 0..1 (64 rows each)
    const int wn = wid & 3;               // 0..3 (32 cols each)
    const int m0 = blockIdx.y * GBM;
    const int n0 = blockIdx.x * GBN;

    const int lrow = tid >> 3;            // 0..31 (x4 iters -> 128 rows)
    const int lseg = tid & 7;             // 16B segment within 128B row

    float acc[4][4][4];
#pragma unroll
    for (int mt = 0; mt < 4; mt++)
#pragma unroll
        for (int nt = 0; nt < 4; nt++)
#pragma unroll
            for (int r = 0; r < 4; r++) acc[mt][nt][r] = 0.f;

    const int chunks = K / GBK;

    // ---- issue chunk c into stage s ----
    auto issue = [&](int c, int s) {
        const uint32_t sa = smb + s * STAGE_BYTES;
        const uint32_t sb = sa + GBM * KPAD * 4;
        const float* Ab = A + (size_t)m0 * K + (size_t)c * GBK;
        const float* Bb = Bw + (size_t)n0 * K + (size_t)c * GBK;
#pragma unroll
        for (int i = 0; i < 4; i++) {
            int row = lrow + i * 32;
            CP_ASYNC16(sa + row * (KPAD * 4) + lseg * 16,
                       Ab + (size_t)row * K + lseg * 4);
            CP_ASYNC16(sb + row * (KPAD * 4) + lseg * 16,
                       Bb + (size_t)row * K + lseg * 4);
        }
        CP_COMMIT();
    };

    issue(0, 0);

    for (int c = 0; c < chunks; c++) {
        const int s = c & 1;
        if (c + 1 < chunks) { issue(c + 1, s ^ 1); CP_WAIT(1); }
        else                { CP_WAIT(0); }
        __syncthreads();

        const float* As = smf + s * STAGE_FLOATS;
        const float* Bs = As + GBM * KPAD;

#pragma unroll
        for (int ks = 0; ks < 4; ks++) {
            const int kk = ks * 8 + 2 * tig;   // k-permuted: logical {tig,tig+4} -> phys {2tig,2tig+1}
            uint32_t a[4][4], b[4][2];
#pragma unroll
            for (int mt = 0; mt < 4; mt++) {
                int mr = wm * 64 + mt * 16 + group;
                float2 v0 = *(const float2*)&As[mr * KPAD + kk];
                float2 v1 = *(const float2*)&As[(mr + 8) * KPAD + kk];
                a[mt][0] = f2tf32(v0.x);
                a[mt][2] = f2tf32(v0.y);
                a[mt][1] = f2tf32(v1.x);
                a[mt][3] = f2tf32(v1.y);
            }
#pragma unroll
            for (int nt = 0; nt < 4; nt++) {
                int nr = wn * 32 + nt * 8 + group;
                float2 v = *(const float2*)&Bs[nr * KPAD + kk];
                b[nt][0] = f2tf32(v.x);
                b[nt][1] = f2tf32(v.y);
            }
#pragma unroll
            for (int mt = 0; mt < 4; mt++)
#pragma unroll
                for (int nt = 0; nt < 4; nt++)
                    mma_tf32(acc[mt][nt], a[mt], b[nt]);
        }
        __syncthreads();
    }

    // Epilogue
#pragma unroll
    for (int mt = 0; mt < 4; mt++) {
        int mr = m0 + wm * 64 + mt * 16 + group;
#pragma unroll
        for (int nt = 0; nt < 4; nt++) {
            int nc = n0 + wn * 32 + nt * 8 + 2 * tig;
            *(float2*)&C[(size_t)mr * N + nc] =
                make_float2(acc[mt][nt][0], acc[mt][nt][1]);
            *(float2*)&C[(size_t)(mr + 8) * N + nc] =
                make_float2(acc[mt][nt][2], acc[mt][nt][3]);
        }
    }
}

// ---------------------------------------------------------------------------
// Per-(token, head) RMSNorm + RoPE, in place on g_qkv.
// ---------------------------------------------------------------------------
__global__ __launch_bounds__(128) void norm_rope(
    float* __restrict__ qkv, const int* __restrict__ positions,
    const float* __restrict__ qw, const float* __restrict__ kw)
{
    const int blk = blockIdx.x;
    const int t = blk / (N_HEADS + N_KV);
    const int hh = blk % (N_HEADS + N_KV);
    float* ptr;
    const float* w;
    if (hh < N_HEADS) {
        ptr = qkv + (size_t)t * QKV_DIM + hh * HEAD_DIM;
        w = qw;
    } else {
        ptr = qkv + (size_t)t * QKV_DIM + Q_SIZE + (hh - N_HEADS) * HEAD_DIM;
        w = kw;
    }
    const int tid = threadIdx.x;
    __shared__ float xs[128];
    __shared__ float red[4];

    float x = ptr[tid];
    float ss = x * x;
#pragma unroll
    for (int o = 16; o > 0; o >>= 1) ss += __shfl_xor_sync(0xffffffffu, ss, o);
    if ((tid & 31) == 0) red[tid >> 5] = ss;
    __syncthreads();
    float tot = red[0] + red[1] + red[2] + red[3];
    float r = rsqrtf(tot * (1.0f / 128.0f) + 1e-6f);
    xs[tid] = x * r * w[tid];
    __syncthreads();

    if (tid < 64) {
        int pos = positions[t];
        double invf = exp(-(double)tid * (13.815510557964274 / 64.0));
        double ang = (double)pos * invf;
        double sd, cd;
        sincos(ang, &sd, &cd);
        float c = (float)cd, s = (float)sd;
        float x1 = xs[tid], x2 = xs[tid + 64];
        ptr[tid]      = x1 * c - x2 * s;
        ptr[tid + 64] = x2 * c + x1 * s;
    }
}

// ---------------------------------------------------------------------------
// Flash attention, fp32, causal, GQA (group = 8). 64x64 tiles, d = 128.
// ---------------------------------------------------------------------------
#define QK_STRIDE 68

__global__ __launch_bounds__(256) void flash_attn(
    const float* __restrict__ qkv, float* __restrict__ attn_out)
{
    extern __shared__ float smf[];
    float* Qts = smf;
    float* Kts = Qts + 128 * QK_STRIDE;
    float* Vs  = Kts + 128 * QK_STRIDE;
    float* Ps  = Vs + 64 * 128;

    const int qt = blockIdx.x;
    const int bh = blockIdx.y;
    const int b = bh >> 5;
    const int h = bh & 31;
    const int kvh = h >> 3;
    const int tid = threadIdx.x;
    const int tx = tid & 15;
    const int ty = tid >> 4;
    const int qm0 = qt * 64;
    const float scale = 0.08838834764831845f;

    const int lr = tid >> 2;
    const int lc = tid & 3;

    const float* qbase = qkv + (size_t)(b * S_LEN + qm0) * QKV_DIM + h * HEAD_DIM;
#pragma unroll
    for (int i = 0; i < 8; i++) {
        int d4 = lc + 4 * i;
        float4 v = *(const float4*)&qbase[(size_t)lr * QKV_DIM + d4 * 4];
        Qts[(d4 * 4 + 0) * QK_STRIDE + lr] = v.x * scale;
        Qts[(d4 * 4 + 1) * QK_STRIDE + lr] = v.y * scale;
        Qts[(d4 * 4 + 2) * QK_STRIDE + lr] = v.z * scale;
        Qts[(d4 * 4 + 3) * QK_STRIDE + lr] = v.w * scale;
    }
    __syncthreads();

    float m_i[4], l_i[4], O[4][8];
#pragma unroll
    for (int i = 0; i < 4; i++) {
        m_i[i] = -1e30f;
        l_i[i] = 0.f;
#pragma unroll
        for (int c = 0; c < 8; c++) O[i][c] = 0.f;
    }

    const float* kbase_all = qkv + (size_t)(b * S_LEN) * QKV_DIM + Q_SIZE + kvh * HEAD_DIM;
    const float* vbase_all = kbase_all + KV_SIZE;

    for (int kt = 0; kt <= qt; kt++) {
        const float* kb = kbase_all + (size_t)kt * 64 * QKV_DIM;
        const float* vb = vbase_all + (size_t)kt * 64 * QKV_DIM;
#pragma unroll
        for (int i = 0; i < 8; i++) {
            int d4 = lc + 4 * i;
            float4 kv4 = *(const float4*)&kb[(size_t)lr * QKV_DIM + d4 * 4];
            Kts[(d4 * 4 + 0) * QK_STRIDE + lr] = kv4.x;
            Kts[(d4 * 4 + 1) * QK_STRIDE + lr] = kv4.y;
            Kts[(d4 * 4 + 2) * QK_STRIDE + lr] = kv4.z;
            Kts[(d4 * 4 + 3) * QK_STRIDE + lr] = kv4.w;
            float4 vv4 = *(const float4*)&vb[(size_t)lr * QKV_DIM + d4 * 4];
            *(float4*)&Vs[lr * 128 + d4 * 4] = vv4;
        }
        __syncthreads();

        float s[4][4];
#pragma unroll
        for (int i = 0; i < 4; i++)
#pragma unroll
            for (int j = 0; j < 4; j++) s[i][j] = 0.f;

#pragma unroll 4
        for (int d = 0; d < 128; d++) {
            float4 qv = *(float4*)&Qts[d * QK_STRIDE + 4 * ty];
            float4 kv = *(float4*)&Kts[d * QK_STRIDE + 4 * tx];
            float qa[4] = {qv.x, qv.y, qv.z, qv.w};
            float ka[4] = {kv.x, kv.y, kv.z, kv.w};
#pragma unroll
            for (int i = 0; i < 4; i++)
#pragma unroll
                for (int j = 0; j < 4; j++)
                    s[i][j] = fmaf(qa[i], ka[j], s[i][j]);
        }

        if (kt == qt) {
#pragma unroll
            for (int i = 0; i < 4; i++)
#pragma unroll
                for (int j = 0; j < 4; j++)
                    if (4 * tx + j > 4 * ty + i) s[i][j] = -1e30f;
        }

#pragma unroll
        for (int i = 0; i < 4; i++) {
            float mx = s[i][0];
            mx = fmaxf(mx, s[i][1]);
            mx = fmaxf(mx, s[i][2]);
            mx = fmaxf(mx, s[i][3]);
#pragma unroll
            for (int o = 8; o > 0; o >>= 1)
                mx = fmaxf(mx, __shfl_xor_sync(0xffffffffu, mx, o, 16));
            float mnew = fmaxf(m_i[i], mx);
            float alpha = __expf(m_i[i] - mnew);
            float rowsum = 0.f;
#pragma unroll
            for (int j = 0; j < 4; j++) {
                float p = __expf(s[i][j] - mnew);
                s[i][j] = p;
                rowsum += p;
            }
#pragma unroll
            for (int o = 8; o > 0; o >>= 1)
                rowsum += __shfl_xor_sync(0xffffffffu, rowsum, o, 16);
            l_i[i] = l_i[i] * alpha + rowsum;
            m_i[i] = mnew;
#pragma unroll
            for (int c = 0; c < 8; c++) O[i][c] *= alpha;
            *(float4*)&Ps[(4 * ty + i) * 64 + 4 * tx] =
                make_float4(s[i][0], s[i][1], s[i][2], s[i][3]);
        }
        __syncthreads();

#pragma unroll 2
        for (int j = 0; j < 64; j++) {
            float p0 = Ps[(4 * ty + 0) * 64 + j];
            float p1 = Ps[(4 * ty + 1) * 64 + j];
            float p2 = Ps[(4 * ty + 2) * 64 + j];
            float p3 = Ps[(4 * ty + 3) * 64 + j];
            float4 va = *(float4*)&Vs[j * 128 + 8 * tx];
            float4 vbv = *(float4*)&Vs[j * 128 + 8 * tx + 4];
            float vv[8] = {va.x, va.y, va.z, va.w, vbv.x, vbv.y, vbv.z, vbv.w};
#pragma unroll
            for (int c = 0; c < 8; c++) {
                O[0][c] = fmaf(p0, vv[c], O[0][c]);
                O[1][c] = fmaf(p1, vv[c], O[1][c]);
                O[2][c] = fmaf(p2, vv[c], O[2][c]);
                O[3][c] = fmaf(p3, vv[c], O[3][c]);
            }
        }
        __syncthreads();
    }

#pragma unroll
    for (int i = 0; i < 4; i++) {
        float inv = 1.0f / l_i[i];
        size_t row = (size_t)(b * S_LEN + qm0 + 4 * ty + i) * Q_SIZE + h * HEAD_DIM + 8 * tx;
        attn_out[row + 0] = O[i][0] * inv;
        attn_out[row + 1] = O[i][1] * inv;
        attn_out[row + 2] = O[i][2] * inv;
        attn_out[row + 3] = O[i][3] * inv;
        attn_out[row + 4] = O[i][4] * inv;
        attn_out[row + 5] = O[i][5] * inv;
        attn_out[row + 6] = O[i][6] * inv;
        attn_out[row + 7] = O[i][7] * inv;
    }
}

// ---------------------------------------------------------------------------
extern "C" void kernel_launch(void* const* d_in, const int* in_sizes, int n_in,
                              void* d_out, int out_size)
{
    const float* hidden    = (const float*)d_in[0];
    const int*   positions = (const int*)d_in[1];
    const float* w_qkv     = (const float*)d_in[2];
    const float* w_o       = (const float*)d_in[3];
    const float* q_norm_w  = (const float*)d_in[4];
    const float* k_norm_w  = (const float*)d_in[5];
    float* out = (float*)d_out;

    float* qkv;
    float* attn;
    cudaGetSymbolAddress((void**)&qkv, g_qkv);
    cudaGetSymbolAddress((void**)&attn, g_attn);

    cudaFuncSetAttribute(gemm_tc, cudaFuncAttributeMaxDynamicSharedMemorySize, GEMM_SMEM);

    // 1) QKV projection: [4096,2048] x [5120,2048]^T -> [4096,5120]  (tf32 mma.sync)
    gemm_tc<<<dim3(QKV_DIM / GBN, TOKENS / GBM), 256, GEMM_SMEM>>>(
        hidden, w_qkv, qkv, TOKENS, QKV_DIM, HIDDEN);

    // 2) RMSNorm + RoPE on q and k heads, in place
    norm_rope<<<TOKENS * (N_HEADS + N_KV), 128>>>(qkv, positions, q_norm_w, k_norm_w);

    // 3) Causal flash attention (fp32)
    const int flash_smem = (2 * 128 * QK_STRIDE + 64 * 128 + 64 * 64) * sizeof(float);
    cudaFuncSetAttribute(flash_attn, cudaFuncAttributeMaxDynamicSharedMemorySize, flash_smem);
    flash_attn<<<dim3(S_LEN / 64, B_SZ * N_HEADS), 256, flash_smem>>>(qkv, attn);

    // 4) Output projection: [4096,4096] x [2048,4096]^T -> [4096,2048]  (tf32 mma.sync)
    gemm_tc<<<dim3(HIDDEN / GBN, TOKENS / GBM), 256, GEMM_SMEM>>>(
        attn, w_o, out, TOKENS, HIDDEN, Q_SIZE);
}

// round 5
// speedup vs baseline: 2.7296x; 1.8077x over previous
#include <cuda_runtime.h>
#include <cuda_bf16.h>
#include <math.h>
#include <cstdint>

#define HIDDEN 2048
#define N_HEADS 32
#define N_KV 4
#define HEAD_DIM 128
#define B_SZ 2
#define S_LEN 2048
#define TOKENS (B_SZ * S_LEN)            // 4096
#define QKV_DIM ((N_HEADS + 2 * N_KV) * HEAD_DIM)  // 5120
#define Q_SIZE (N_HEADS * HEAD_DIM)      // 4096
#define KV_SIZE (N_KV * HEAD_DIM)        // 512

// Scratch
__device__ float g_qkv[(size_t)TOKENS * QKV_DIM];   // ~84 MB
__device__ float g_attn[(size_t)TOKENS * Q_SIZE];   // ~67 MB

// ---------------------------------------------------------------------------
// Helpers
// ---------------------------------------------------------------------------
static __device__ __forceinline__ uint32_t smem_u32(const void* p) {
    uint32_t a;
    asm("{ .reg .u64 t; cvta.to.shared.u64 t, %1; cvt.u32.u64 %0, t; }" : "=r"(a) : "l"(p));
    return a;
}
static __device__ __forceinline__ uint32_t f2tf32(float x) {
    uint32_t r;
    asm("cvt.rna.tf32.f32 %0, %1;" : "=r"(r) : "f"(x));
    return r;
}
#define CP_ASYNC16(dst, src) \
    asm volatile("cp.async.cg.shared.global [%0], [%1], 16;" :: "r"(dst), "l"(src) : "memory")
#define CP_COMMIT() asm volatile("cp.async.commit_group;" ::: "memory")
#define CP_WAIT(n)  asm volatile("cp.async.wait_group %0;" :: "n"(n) : "memory")

// m16n8k8 tf32 mma.sync (row.col): D += A * B
static __device__ __forceinline__ void mma_tf32(
    float* c, const uint32_t* a, const uint32_t* b)
{
    asm volatile(
        "mma.sync.aligned.m16n8k8.row.col.f32.tf32.tf32.f32 "
        "{%0,%1,%2,%3}, {%4,%5,%6,%7}, {%8,%9}, {%0,%1,%2,%3};"
        : "+f"(c[0]), "+f"(c[1]), "+f"(c[2]), "+f"(c[3])
        : "r"(a[0]), "r"(a[1]), "r"(a[2]), "r"(a[3]), "r"(b[0]), "r"(b[1]));
}

// ---------------------------------------------------------------------------
// tf32 mma.sync GEMM: C[M,N] = A[M,K] * B[N,K]^T (row-major, K contiguous)
// ---------------------------------------------------------------------------
#define GBM 128
#define GBN 128
#define GBK 32
#define KPAD 40
#define STAGE_FLOATS ((GBM + GBN) * KPAD)
#define STAGE_BYTES (STAGE_FLOATS * 4)
#define GEMM_SMEM (2 * STAGE_BYTES)

__global__ __launch_bounds__(256) void gemm_tc(
    const float* __restrict__ A, const float* __restrict__ Bw,
    float* __restrict__ C, int M, int N, int K)
{
    extern __shared__ float smf[];
    const uint32_t smb = smem_u32(smf);
    const int tid = threadIdx.x;
    const int wid = tid >> 5;
    const int lane = tid & 31;
    const int group = lane >> 2;
    const int tig = lane & 3;
    const int wm = wid >> 2;
    const int wn = wid & 3;
    const int m0 = blockIdx.y * GBM;
    const int n0 = blockIdx.x * GBN;

    const int lrow = tid >> 3;
    const int lseg = tid & 7;

    float acc[4][4][4];
#pragma unroll
    for (int mt = 0; mt < 4; mt++)
#pragma unroll
        for (int nt = 0; nt < 4; nt++)
#pragma unroll
            for (int r = 0; r < 4; r++) acc[mt][nt][r] = 0.f;

    const int chunks = K / GBK;

    auto issue = [&](int c, int s) {
        const uint32_t sa = smb + s * STAGE_BYTES;
        const uint32_t sb = sa + GBM * KPAD * 4;
        const float* Ab = A + (size_t)m0 * K + (size_t)c * GBK;
        const float* Bb = Bw + (size_t)n0 * K + (size_t)c * GBK;
#pragma unroll
        for (int i = 0; i < 4; i++) {
            int row = lrow + i * 32;
            CP_ASYNC16(sa + row * (KPAD * 4) + lseg * 16,
                       Ab + (size_t)row * K + lseg * 4);
            CP_ASYNC16(sb + row * (KPAD * 4) + lseg * 16,
                       Bb + (size_t)row * K + lseg * 4);
        }
        CP_COMMIT();
    };

    issue(0, 0);

    for (int c = 0; c < chunks; c++) {
        const int s = c & 1;
        if (c + 1 < chunks) { issue(c + 1, s ^ 1); CP_WAIT(1); }
        else                { CP_WAIT(0); }
        __syncthreads();

        const float* As = smf + s * STAGE_FLOATS;
        const float* Bs = As + GBM * KPAD;

#pragma unroll
        for (int ks = 0; ks < 4; ks++) {
            const int kk = ks * 8 + 2 * tig;
            uint32_t a[4][4], b[4][2];
#pragma unroll
            for (int mt = 0; mt < 4; mt++) {
                int mr = wm * 64 + mt * 16 + group;
                float2 v0 = *(const float2*)&As[mr * KPAD + kk];
                float2 v1 = *(const float2*)&As[(mr + 8) * KPAD + kk];
                a[mt][0] = f2tf32(v0.x);
                a[mt][2] = f2tf32(v0.y);
                a[mt][1] = f2tf32(v1.x);
                a[mt][3] = f2tf32(v1.y);
            }
#pragma unroll
            for (int nt = 0; nt < 4; nt++) {
                int nr = wn * 32 + nt * 8 + group;
                float2 v = *(const float2*)&Bs[nr * KPAD + kk];
                b[nt][0] = f2tf32(v.x);
                b[nt][1] = f2tf32(v.y);
            }
#pragma unroll
            for (int mt = 0; mt < 4; mt++)
#pragma unroll
                for (int nt = 0; nt < 4; nt++)
                    mma_tf32(acc[mt][nt], a[mt], b[nt]);
        }
        __syncthreads();
    }

#pragma unroll
    for (int mt = 0; mt < 4; mt++) {
        int mr = m0 + wm * 64 + mt * 16 + group;
#pragma unroll
        for (int nt = 0; nt < 4; nt++) {
            int nc = n0 + wn * 32 + nt * 8 + 2 * tig;
            *(float2*)&C[(size_t)mr * N + nc] =
                make_float2(acc[mt][nt][0], acc[mt][nt][1]);
            *(float2*)&C[(size_t)(mr + 8) * N + nc] =
                make_float2(acc[mt][nt][2], acc[mt][nt][3]);
        }
    }
}

// ---------------------------------------------------------------------------
// Per-(token, head) RMSNorm + RoPE, in place on g_qkv.
// ---------------------------------------------------------------------------
__global__ __launch_bounds__(128) void norm_rope(
    float* __restrict__ qkv, const int* __restrict__ positions,
    const float* __restrict__ qw, const float* __restrict__ kw)
{
    const int blk = blockIdx.x;
    const int t = blk / (N_HEADS + N_KV);
    const int hh = blk % (N_HEADS + N_KV);
    float* ptr;
    const float* w;
    if (hh < N_HEADS) {
        ptr = qkv + (size_t)t * QKV_DIM + hh * HEAD_DIM;
        w = qw;
    } else {
        ptr = qkv + (size_t)t * QKV_DIM + Q_SIZE + (hh - N_HEADS) * HEAD_DIM;
        w = kw;
    }
    const int tid = threadIdx.x;
    __shared__ float xs[128];
    __shared__ float red[4];

    float x = ptr[tid];
    float ss = x * x;
#pragma unroll
    for (int o = 16; o > 0; o >>= 1) ss += __shfl_xor_sync(0xffffffffu, ss, o);
    if ((tid & 31) == 0) red[tid >> 5] = ss;
    __syncthreads();
    float tot = red[0] + red[1] + red[2] + red[3];
    float r = rsqrtf(tot * (1.0f / 128.0f) + 1e-6f);
    xs[tid] = x * r * w[tid];
    __syncthreads();

    if (tid < 64) {
        int pos = positions[t];
        double invf = exp(-(double)tid * (13.815510557964274 / 64.0));
        double ang = (double)pos * invf;
        double sd, cd;
        sincos(ang, &sd, &cd);
        float c = (float)cd, s = (float)sd;
        float x1 = xs[tid], x2 = xs[tid + 64];
        ptr[tid]      = x1 * c - x2 * s;
        ptr[tid + 64] = x2 * c + x1 * s;
    }
}

// ---------------------------------------------------------------------------
// Tensor-core flash attention (tf32 mma.sync), causal, GQA group 8.
// CTA: 128 q-rows of one (b,h). 8 warps; warp w owns q-rows [16w,16w+16).
// Key tile 64, cp.async double-buffered K/V. Q pre-rounded in smem.
// ---------------------------------------------------------------------------
#define FA_QSTRIDE 136
#define FA_KSTRIDE 136
#define FA_Q_FLOATS (128 * FA_QSTRIDE)             // 17408
#define FA_KV_FLOATS (64 * FA_KSTRIDE)             // 8704
#define FA_SMEM ((FA_Q_FLOATS + 4 * FA_KV_FLOATS) * 4)  // 208896 B

__global__ __launch_bounds__(256, 1) void flash_tc(
    const float* __restrict__ qkv, float* __restrict__ attn_out)
{
    extern __shared__ float smf[];
    float* Qs = smf;                                 // [128][136] tf32-rounded, scaled
    float* Ks[2] = { Qs + FA_Q_FLOATS, Qs + FA_Q_FLOATS + FA_KV_FLOATS };
    float* Vs[2] = { Qs + FA_Q_FLOATS + 2 * FA_KV_FLOATS,
                     Qs + FA_Q_FLOATS + 3 * FA_KV_FLOATS };
    const uint32_t smb = smem_u32(smf);
    const uint32_t ks_off[2] = { (uint32_t)(FA_Q_FLOATS * 4),
                                 (uint32_t)((FA_Q_FLOATS + FA_KV_FLOATS) * 4) };
    const uint32_t vs_off[2] = { (uint32_t)((FA_Q_FLOATS + 2 * FA_KV_FLOATS) * 4),
                                 (uint32_t)((FA_Q_FLOATS + 3 * FA_KV_FLOATS) * 4) };

    const int qi = (int)(gridDim.x - 1 - blockIdx.x);   // largest tile first
    const int bh = blockIdx.y;
    const int b = bh >> 5;
    const int h = bh & 31;
    const int kvh = h >> 3;
    const int tid = threadIdx.x;
    const int wid = tid >> 5;
    const int lane = tid & 31;
    const int group = lane >> 2;
    const int tig = lane & 3;
    const int qm0 = qi * 128;
    const float scale = 0.08838834764831845f;

    // ---- load Q tile (scaled + tf32-rounded) ----
    const float* qbase = qkv + (size_t)(b * S_LEN + qm0) * QKV_DIM + h * HEAD_DIM;
#pragma unroll
    for (int i = 0; i < 16; i++) {
        int f = tid + i * 256;             // 0..4095 float4 units
        int row = f >> 5, c4 = f & 31;
        float4 v = *(const float4*)&qbase[(size_t)row * QKV_DIM + c4 * 4];
        float* d = &Qs[row * FA_QSTRIDE + c4 * 4];
        d[0] = __uint_as_float(f2tf32(v.x * scale));
        d[1] = __uint_as_float(f2tf32(v.y * scale));
        d[2] = __uint_as_float(f2tf32(v.z * scale));
        d[3] = __uint_as_float(f2tf32(v.w * scale));
    }

    const float* kbase = qkv + (size_t)(b * S_LEN) * QKV_DIM + Q_SIZE + kvh * HEAD_DIM;
    const float* vbase = kbase + KV_SIZE;
    const int ntiles = 2 * qi + 2;

    // issue K/V tile kt into stage s (full 128-float rows: 8 float4 per thread each)
    auto issue = [&](int kt, int s) {
        const int lrow = tid >> 2;         // 0..63
        const int lseg = tid & 3;          // 4 threads per row
        const float* kb = kbase + (size_t)(kt * 64) * QKV_DIM;
        const float* vb = vbase + (size_t)(kt * 64) * QKV_DIM;
        uint32_t kd = smb + ks_off[s] + lrow * (FA_KSTRIDE * 4);
        uint32_t vd = smb + vs_off[s] + lrow * (FA_KSTRIDE * 4);
        const float* ksrc = kb + (size_t)lrow * QKV_DIM;
        const float* vsrc = vb + (size_t)lrow * QKV_DIM;
#pragma unroll
        for (int i = 0; i < 8; i++) {
            int c = lseg * 4 + i * 16;     // float index 0..124: 32 float4 per row total
            CP_ASYNC16(kd + c * 4, ksrc + c);
            CP_ASYNC16(vd + c * 4, vsrc + c);
        }
        CP_COMMIT();
    };

    issue(0, 0);
    __syncthreads();   // Q ready (also covers smem write visibility)

    float m_i[2] = {-1e30f, -1e30f};
    float l_i[2] = {0.f, 0.f};
    float O[16][4];
#pragma unroll
    for (int nt = 0; nt < 16; nt++)
#pragma unroll
        for (int r = 0; r < 4; r++) O[nt][r] = 0.f;

    const int qrow_base = wid * 16 + group;      // warp-local q rows (+0 / +8)

    for (int kt = 0; kt < ntiles; kt++) {
        const int s = kt & 1;
        if (kt + 1 < ntiles) { issue(kt + 1, s ^ 1); CP_WAIT(1); }
        else                 { CP_WAIT(0); }
        __syncthreads();

        const float* Kst = Ks[s];
        const float* Vst = Vs[s];

        // ---- S = Q K^T : 8 n-tiles of 8 keys, 16 k-steps over d ----
        float S[8][4];
#pragma unroll
        for (int nt = 0; nt < 8; nt++)
#pragma unroll
            for (int r = 0; r < 4; r++) S[nt][r] = 0.f;

#pragma unroll
        for (int ks = 0; ks < 16; ks++) {
            const int kk = ks * 8 + 2 * tig;
            uint32_t a[4];
            {
                float2 v0 = *(const float2*)&Qs[qrow_base * FA_QSTRIDE + kk];
                float2 v1 = *(const float2*)&Qs[(qrow_base + 8) * FA_QSTRIDE + kk];
                a[0] = __float_as_uint(v0.x);
                a[1] = __float_as_uint(v1.x);
                a[2] = __float_as_uint(v0.y);
                a[3] = __float_as_uint(v1.y);
            }
#pragma unroll
            for (int nt = 0; nt < 8; nt++) {
                float2 w = *(const float2*)&Kst[(nt * 8 + group) * FA_KSTRIDE + kk];
                uint32_t bfr[2] = { f2tf32(w.x), f2tf32(w.y) };
                mma_tf32(S[nt], a, bfr);
            }
        }

        // ---- causal mask on boundary tiles ----
        if (kt >= 2 * qi) {
            const int q0 = qm0 + qrow_base;
            const int kbase_g = kt * 64 + 2 * tig;
#pragma unroll
            for (int nt = 0; nt < 8; nt++) {
                int k0 = kbase_g + nt * 8;
                if (k0 > q0)     S[nt][0] = -1e30f;
                if (k0 + 1 > q0) S[nt][1] = -1e30f;
                if (k0 > q0 + 8)     S[nt][2] = -1e30f;
                if (k0 + 1 > q0 + 8) S[nt][3] = -1e30f;
            }
        }

        // ---- online softmax (rows r0=qrow_base, r1=+8) ----
        float mx0 = -1e30f, mx1 = -1e30f;
#pragma unroll
        for (int nt = 0; nt < 8; nt++) {
            mx0 = fmaxf(mx0, fmaxf(S[nt][0], S[nt][1]));
            mx1 = fmaxf(mx1, fmaxf(S[nt][2], S[nt][3]));
        }
        mx0 = fmaxf(mx0, __shfl_xor_sync(0xffffffffu, mx0, 1));
        mx0 = fmaxf(mx0, __shfl_xor_sync(0xffffffffu, mx0, 2));
        mx1 = fmaxf(mx1, __shfl_xor_sync(0xffffffffu, mx1, 1));
        mx1 = fmaxf(mx1, __shfl_xor_sync(0xffffffffu, mx1, 2));

        float mn0 = fmaxf(m_i[0], mx0);
        float mn1 = fmaxf(m_i[1], mx1);
        float al0 = __expf(m_i[0] - mn0);
        float al1 = __expf(m_i[1] - mn1);
        m_i[0] = mn0; m_i[1] = mn1;

        float sum0 = 0.f, sum1 = 0.f;
#pragma unroll
        for (int nt = 0; nt < 8; nt++) {
            float p0 = __expf(S[nt][0] - mn0);
            float p1 = __expf(S[nt][1] - mn0);
            float p2 = __expf(S[nt][2] - mn1);
            float p3 = __expf(S[nt][3] - mn1);
            sum0 += p0 + p1;
            sum1 += p2 + p3;
            S[nt][0] = __uint_as_float(f2tf32(p0));
            S[nt][1] = __uint_as_float(f2tf32(p1));
            S[nt][2] = __uint_as_float(f2tf32(p2));
            S[nt][3] = __uint_as_float(f2tf32(p3));
        }
        sum0 += __shfl_xor_sync(0xffffffffu, sum0, 1);
        sum0 += __shfl_xor_sync(0xffffffffu, sum0, 2);
        sum1 += __shfl_xor_sync(0xffffffffu, sum1, 1);
        sum1 += __shfl_xor_sync(0xffffffffu, sum1, 2);
        l_i[0] = l_i[0] * al0 + sum0;
        l_i[1] = l_i[1] * al1 + sum1;

#pragma unroll
        for (int nt = 0; nt < 16; nt++) {
            O[nt][0] *= al0; O[nt][1] *= al0;
            O[nt][2] *= al1; O[nt][3] *= al1;
        }

        // ---- O += P V : P fragments = S accum (k-permuted), V from smem ----
#pragma unroll
        for (int ks2 = 0; ks2 < 8; ks2++) {
            uint32_t a[4] = { __float_as_uint(S[ks2][0]), __float_as_uint(S[ks2][2]),
                              __float_as_uint(S[ks2][1]), __float_as_uint(S[ks2][3]) };
            const int vrow = ks2 * 8 + 2 * tig;
#pragma unroll
            for (int nt = 0; nt < 16; nt++) {
                int vcol = nt * 8 + group;
                uint32_t bfr[2] = {
                    f2tf32(Vst[vrow * FA_KSTRIDE + vcol]),
                    f2tf32(Vst[(vrow + 1) * FA_KSTRIDE + vcol]) };
                mma_tf32(O[nt], a, bfr);
            }
        }
        __syncthreads();   // all warps done with stage s before it is re-filled
    }

    // ---- epilogue ----
    float inv0 = 1.f / l_i[0];
    float inv1 = 1.f / l_i[1];
    const size_t orow0 = (size_t)(b * S_LEN + qm0 + qrow_base) * Q_SIZE + h * HEAD_DIM;
    const size_t orow1 = orow0 + 8 * Q_SIZE;
#pragma unroll
    for (int nt = 0; nt < 16; nt++) {
        int nc = nt * 8 + 2 * tig;
        *(float2*)&attn_out[orow0 + nc] = make_float2(O[nt][0] * inv0, O[nt][1] * inv0);
        *(float2*)&attn_out[orow1 + nc] = make_float2(O[nt][2] * inv1, O[nt][3] * inv1);
    }
}

// ---------------------------------------------------------------------------
extern "C" void kernel_launch(void* const* d_in, const int* in_sizes, int n_in,
                              void* d_out, int out_size)
{
    const float* hidden    = (const float*)d_in[0];
    const int*   positions = (const int*)d_in[1];
    const float* w_qkv     = (const float*)d_in[2];
    const float* w_o       = (const float*)d_in[3];
    const float* q_norm_w  = (const float*)d_in[4];
    const float* k_norm_w  = (const float*)d_in[5];
    float* out = (float*)d_out;

    float* qkv;
    float* attn;
    cudaGetSymbolAddress((void**)&qkv, g_qkv);
    cudaGetSymbolAddress((void**)&attn, g_attn);

    cudaFuncSetAttribute(gemm_tc, cudaFuncAttributeMaxDynamicSharedMemorySize, GEMM_SMEM);
    cudaFuncSetAttribute(flash_tc, cudaFuncAttributeMaxDynamicSharedMemorySize, FA_SMEM);

    // 1) QKV projection (tf32 mma.sync)
    gemm_tc<<<dim3(QKV_DIM / GBN, TOKENS / GBM), 256, GEMM_SMEM>>>(
        hidden, w_qkv, qkv, TOKENS, QKV_DIM, HIDDEN);

    // 2) RMSNorm + RoPE
    norm_rope<<<TOKENS * (N_HEADS + N_KV), 128>>>(qkv, positions, q_norm_w, k_norm_w);

    // 3) Causal flash attention (tf32 mma.sync)
    flash_tc<<<dim3(S_LEN / 128, B_SZ * N_HEADS), 256, FA_SMEM>>>(qkv, attn);

    // 4) Output projection (tf32 mma.sync)
    gemm_tc<<<dim3(HIDDEN / GBN, TOKENS / GBM), 256, GEMM_SMEM>>>(
        attn, w_o, out, TOKENS, HIDDEN, Q_SIZE);
}